// round 10
// baseline (speedup 1.0000x reference)
#include <cuda_runtime.h>
#include <cstdint>

#define BATCH 16
#define NPROP 2048
#define NCLS 80
#define NCLS1 81
#define KTOP 2048
#define CAP 16384
#define SCORE_THR 0.05f
#define IOU_THR 0.5f
#define MAXR 4.135166556742356f
#define OUTK 100
#define HISTN 3072
#define BINS 2304
#define SLOTS 4096
#define NT 1024
#define NBLK 3          // blocks per image
#define CPB 32          // classes per block (one per warp)

typedef unsigned long long ull;
typedef unsigned char uchar;

// ---------------- device scratch ----------------
__device__ ull g_keys[BATCH][CAP];
__device__ int g_cnt[BATCH];            // zero-init; reset by emitter block
__device__ uchar g_alive[BATCH][KTOP];  // only cross-block state
__device__ int g_done[BATCH];           // zero-init; reset by emitter block

__device__ __forceinline__ int score_bin(unsigned u) {
    int bn = (int)(u >> 14) - 62770;
    return min(max(bn, 0), BINS - 1);
}

// ---------------- 1: softmax + threshold + block-aggregated compaction ----------------
__global__ void k_softmax_compact(const float* __restrict__ cls) {
    __shared__ int s_cnt, s_base;
    __shared__ ull s_buf[176];
    int tid = threadIdx.x;
    int lane = tid & 31;
    int w = tid >> 5;
    int gw = blockIdx.x * 8 + w;
    int b = gw >> 11;
    int n = gw & (NPROP - 1);

    if (tid == 0) s_cnt = 0;
    __syncthreads();

    const float* x = cls + (size_t)gw * NCLS1;
    float v0 = x[lane];
    float v1 = x[lane + 32];
    float v2 = (lane < 17) ? x[lane + 64] : -3.4e38f;
    float m = fmaxf(fmaxf(v0, v1), v2);
#pragma unroll
    for (int o = 16; o > 0; o >>= 1) m = fmaxf(m, __shfl_xor_sync(0xffffffffu, m, o));
    float e0 = expf(v0 - m);
    float e1 = expf(v1 - m);
    float e2 = (lane < 17) ? expf(v2 - m) : 0.0f;
    float s = e0 + e1 + e2;
#pragma unroll
    for (int o = 16; o > 0; o >>= 1) s += __shfl_xor_sync(0xffffffffu, s, o);

    auto push = [&](bool cond, float p, unsigned idx) {
        unsigned mask = __ballot_sync(0xffffffffu, cond);
        if (cond) {
            unsigned u = __float_as_uint(p);
            int leader = __ffs(mask) - 1;
            int base = 0;
            if (lane == leader) base = atomicAdd(&s_cnt, __popc(mask));
            base = __shfl_sync(mask, base, leader);
            s_buf[base + __popc(mask & ((1u << lane) - 1))] = ((ull)(~u) << 32) | idx;
        }
    };
    float p0 = e0 / s;
    push(p0 > SCORE_THR, p0, (unsigned)(n * NCLS + lane));
    float p1 = e1 / s;
    push(p1 > SCORE_THR, p1, (unsigned)(n * NCLS + lane + 32));
    float p2 = e2 / s;
    push((lane < 16) && (p2 > SCORE_THR), p2, (unsigned)(n * NCLS + lane + 64));
    __syncthreads();

    if (tid == 0) s_base = atomicAdd(&g_cnt[b], s_cnt);
    __syncthreads();
    int cnt = s_cnt, base = s_base;
    for (int i = tid; i < cnt; i += 256)
        if (base + i < CAP) g_keys[b][base + i] = s_buf[i];
}

// ---------------- 2: fused select+sort+decode+NMS+output ----------------
// grid = BATCH*NBLK; each block redundantly selects/sorts/decodes its image
// in smem, then NMS's its 32 classes; last block per image emits.
// dynamic smem layout (bytes):
//   tmpk   @0       32768   ull[4096]
//   hist   @32768   12288
//   base   @45056   12288
//   sb     @57344   32768   float4[2048] offset boxes (NMS space)
//   sbout  @90112   32768   float4[2048] clipped boxes (output)
//   skey   @122880  16384   ull[2048] sorted keys
//   slab   @139264  2048
//   salive @141312  2048
//   clist  @143360  4096    short[2048]
#define SMEM_NDO 147456
extern __shared__ char dynndo[];

__global__ void __launch_bounds__(NT) k_ndo(const float* __restrict__ reg,
                                            const float* __restrict__ props,
                                            const int* __restrict__ hw,
                                            float* __restrict__ out) {
    int b = blockIdx.x / NBLK;
    int cg = blockIdx.x % NBLK;
    int tid = threadIdx.x;
    int lane = tid & 31;
    int warp = tid >> 5;

    ull* tmpk = (ull*)dynndo;
    int* hist = (int*)(dynndo + 32768);
    int* base = (int*)(dynndo + 45056);
    float4* sb = (float4*)(dynndo + 57344);
    float4* sbout = (float4*)(dynndo + 90112);
    ull* skey = (ull*)(dynndo + 122880);
    uchar* slab = (uchar*)(dynndo + 139264);
    uchar* salive = (uchar*)(dynndo + 141312);
    short* clist = (short*)(dynndo + 143360);

    __shared__ int s_wsum[32];
    __shared__ int s_ccnt[CPB], s_cbase[CPB];
    __shared__ int s_last, s_total;

    int cnt = min(g_cnt[b], CAP);

    // ---- smem histogram of this image's keys ----
    for (int i = tid; i < HISTN; i += NT) hist[i] = 0;
    __syncthreads();
    for (int i = tid; i < cnt; i += NT)
        atomicAdd(&hist[score_bin(~(unsigned)(g_keys[b][i] >> 32))], 1);
    __syncthreads();

    // ---- hierarchical suffix scan: base[bb] = # candidates in bins > bb ----
    int h0 = hist[3 * tid], h1 = hist[3 * tid + 1], h2 = hist[3 * tid + 2];
    int loc = h0 + h1 + h2;
    int v = loc;
#pragma unroll
    for (int o = 1; o < 32; o <<= 1) {
        int u = __shfl_down_sync(0xffffffffu, v, o);
        if (lane + o < 32) v += u;
    }
    if (lane == 0) s_wsum[warp] = v;
    __syncthreads();
    if (warp == 0) {
        int wv = s_wsum[lane];
#pragma unroll
        for (int o = 1; o < 32; o <<= 1) {
            int u = __shfl_down_sync(0xffffffffu, wv, o);
            if (lane + o < 32) wv += u;
        }
        s_wsum[lane] = wv;
    }
    __syncthreads();
    int beyondW = (warp < 31) ? s_wsum[warp + 1] : 0;
    int beyond = v + beyondW - loc;
    base[3 * tid + 2] = beyond;
    base[3 * tid + 1] = beyond + h2;
    base[3 * tid] = beyond + h2 + h1;
    int S_total = s_wsum[0];
    __syncthreads();

    // ---- scatter to bin-grouped slots ----
    for (int i = tid; i < HISTN; i += NT) hist[i] = 0;
    __syncthreads();
    for (int i = tid; i < cnt; i += NT) {
        ull k = g_keys[b][i];
        int bb = score_bin(~(unsigned)(k >> 32));
        int st = base[bb];
        if (st >= SLOTS) continue;
        int pos = st + atomicAdd(&hist[bb], 1);
        if (pos < SLOTS) tmpk[pos] = k;
    }
    __syncthreads();

    int validcnt = min(S_total, KTOP);

    float h = (float)hw[b * 2];
    float w = (float)hw[b * 2 + 1];
    float offmul = fmaxf(w, h) + 1.0f;

    // ---- fused exact-rank placement + decode into smem ----
    int S_use = min(S_total, SLOTS);
    for (int i = tid; i < S_use; i += NT) {
        ull key = tmpk[i];
        int bb = score_bin(~(unsigned)(key >> 32));
        int st = base[bb];
        if (st >= KTOP) continue;
        int en = min(st + hist[bb], SLOTS);
        int r = 0;
        for (int j = st; j < en; j++) r += (tmpk[j] < key);
        int pos = st + r;
        if (pos >= KTOP) continue;

        unsigned idx = (unsigned)key;
        int n = (int)(idx / NCLS);
        int c = (int)(idx % NCLS);
        const float* pr = props + ((size_t)b * NPROP + n) * 4;
        float p0 = pr[0], p1 = pr[1], p2 = pr[2], p3 = pr[3];
        float px = (p0 + p2) * 0.5f;
        float py = (p1 + p3) * 0.5f;
        float pw = p2 - p0;
        float ph = p3 - p1;
        const float* dd = reg + ((size_t)b * NPROP + n) * (NCLS * 4) + c * 4;
        float dx = dd[0] * 0.1f;
        float dy = dd[1] * 0.1f;
        float dw = fminf(fmaxf(dd[2] * 0.2f, -MAXR), MAXR);
        float dh = fminf(fmaxf(dd[3] * 0.2f, -MAXR), MAXR);
        float gw = pw * expf(dw);
        float gh = ph * expf(dh);
        float gx = px + pw * dx;
        float gy = py + ph * dy;
        float x1 = fminf(fmaxf(gx - 0.5f * gw, 0.f), w);
        float y1 = fminf(fmaxf(gy - 0.5f * gh, 0.f), h);
        float x2 = fminf(fmaxf(gx + 0.5f * gw, 0.f), w);
        float y2 = fminf(fmaxf(gy + 0.5f * gh, 0.f), h);
        float off = (float)c * offmul;
        skey[pos] = key;
        sbout[pos] = make_float4(x1, y1, x2, y2);
        sb[pos] = make_float4(x1 + off, y1 + off, x2 + off, y2 + off);
        slab[pos] = (uchar)c;
        salive[pos] = 1;
    }
    for (int i = validcnt + tid; i < KTOP; i += NT) {
        slab[i] = 255;
        salive[i] = 0;
    }
    __syncthreads();

    // ---- per-class NMS: warp w handles class cg*32 + w ----
    int c = cg * CPB + warp;
    bool haveC = (c < NCLS);
    int n2 = 0;
    for (int k0 = 0; k0 < validcnt; k0 += 32) {
        bool mine = haveC && (k0 + lane < validcnt) && ((int)slab[k0 + lane] == c);
        n2 += __popc(__ballot_sync(0xffffffffu, mine));
    }
    if (lane == 0) s_ccnt[warp] = n2;
    __syncthreads();
    if (tid == 0) {
        int acc = 0;
        for (int k = 0; k < CPB; k++) { s_cbase[k] = acc; acc += s_ccnt[k]; }
    }
    __syncthreads();
    int cb = s_cbase[warp];

    int wr = 0;
    for (int k0 = 0; k0 < validcnt; k0 += 32) {
        bool mine = haveC && (k0 + lane < validcnt) && ((int)slab[k0 + lane] == c);
        unsigned mm = __ballot_sync(0xffffffffu, mine);
        if (mine) clist[cb + wr + __popc(mm & ((1u << lane) - 1))] = (short)(k0 + lane);
        wr += __popc(mm);
    }
    __syncwarp(0xffffffffu);

    for (int s2 = 0; s2 < n2; s2++) {
        int is = clist[cb + s2];
        if (!salive[is]) continue;
        float4 A = sb[is];
        float areaA = fmaxf(A.z - A.x, 0.f) * fmaxf(A.w - A.y, 0.f);
        for (int t = s2 + 1 + lane; t < n2; t += 32) {
            int jt = clist[cb + t];
            if (!salive[jt]) continue;
            float4 q = sb[jt];
            float inter = fmaxf(fminf(A.z, q.z) - fmaxf(A.x, q.x), 0.f) *
                          fmaxf(fminf(A.w, q.w) - fmaxf(A.y, q.y), 0.f);
            float areaB = fmaxf(q.z - q.x, 0.f) * fmaxf(q.w - q.y, 0.f);
            float uni = areaA + areaB - inter;
            if (uni > 0.f && inter > IOU_THR * uni) salive[jt] = 0;
        }
        __syncwarp(0xffffffffu);
    }
    // publish this block's classes' final alive flags
    for (int t = lane; t < n2; t += 32) {
        int i = clist[cb + t];
        g_alive[b][i] = salive[i];
    }
    __syncthreads();

    // ---- last block per image emits output ----
    if (tid == 0) {
        __threadfence();
        int old = atomicAdd(&g_done[b], 1);
        s_last = (old == NBLK - 1);
    }
    __syncthreads();
    if (!s_last) return;
    __threadfence();   // acquire other blocks' g_alive writes
    if (tid == 0) { g_done[b] = 0; g_cnt[b] = 0; }

    int i0 = 2 * tid, i1 = 2 * tid + 1;
    int a0 = (i0 < validcnt) ? g_alive[b][i0] : 0;
    int a1 = (i1 < validcnt) ? g_alive[b][i1] : 0;
    int ps = a0 + a1;
    int sc = ps;
#pragma unroll
    for (int o = 1; o < 32; o <<= 1) {
        int u = __shfl_up_sync(0xffffffffu, sc, o);
        if (lane >= o) sc += u;
    }
    if (lane == 31) s_wsum[warp] = sc;
    __syncthreads();
    if (warp == 0) {
        int wv = s_wsum[lane];
#pragma unroll
        for (int o = 1; o < 32; o <<= 1) {
            int u = __shfl_up_sync(0xffffffffu, wv, o);
            if (lane >= o) wv += u;
        }
        s_wsum[lane] = wv;
        if (lane == 31) s_total = wv;
    }
    __syncthreads();
    int wbase = warp ? s_wsum[warp - 1] : 0;
    int excl = wbase + sc - ps;

    if (a0 && excl < OUTK) {
        ull key = skey[i0];
        ((float4*)out)[b * OUTK + excl] = sbout[i0];
        out[BATCH * OUTK * 4 + b * OUTK + excl] = __uint_as_float(~(unsigned)(key >> 32));
        out[BATCH * OUTK * 5 + b * OUTK + excl] = (float)((unsigned)key % NCLS);
    }
    int r1 = excl + a0;
    if (a1 && r1 < OUTK) {
        ull key = skey[i1];
        ((float4*)out)[b * OUTK + r1] = sbout[i1];
        out[BATCH * OUTK * 4 + b * OUTK + r1] = __uint_as_float(~(unsigned)(key >> 32));
        out[BATCH * OUTK * 5 + b * OUTK + r1] = (float)((unsigned)key % NCLS);
    }
    int kept = min(s_total, OUTK);
    for (int r = kept + tid; r < OUTK; r += NT) {
        ((float4*)out)[b * OUTK + r] = make_float4(0.f, 0.f, 0.f, 0.f);
        out[BATCH * OUTK * 4 + b * OUTK + r] = 0.0f;
        out[BATCH * OUTK * 5 + b * OUTK + r] = -1.0f;
    }
}

// ---------------- launch ----------------
extern "C" void kernel_launch(void* const* d_in, const int* in_sizes, int n_in,
                              void* d_out, int out_size) {
    const float* cls = (const float*)d_in[0];   // [16,2048,81]
    const float* reg = (const float*)d_in[1];   // [16,2048,320]
    const float* props = (const float*)d_in[2]; // [16,2048,4]
    const int* hw = (const int*)d_in[3];        // [16,2]
    float* out = (float*)d_out;

    cudaFuncSetAttribute(k_ndo,
                         cudaFuncAttributeMaxDynamicSharedMemorySize, SMEM_NDO);

    k_softmax_compact<<<BATCH * NPROP / 8, 256>>>(cls);
    k_ndo<<<BATCH * NBLK, NT, SMEM_NDO>>>(reg, props, hw, out);
}